// round 15
// baseline (speedup 1.0000x reference)
#include <cuda_runtime.h>
#include <cuda_fp16.h>
#include <cstdint>

// LightGCN: out = 0.25*(X + h1 + h2 + h3), h_{k+1} = A h_k
// Pull-based CSR, fp16 gathers/intermediates, fp32 accumulation.
// R15 = R14 kernel bodies + Programmatic Dependent Launch (PDL) chaining:
// each kernel triggers launch_dependents after its final stores; successors
// begin scheduling during the predecessor's tail -> hides the 5 boundary gaps.

#define N_NODES 100000
#define D_FEAT  64
#define MAX_E   1600000
#define SCAN_BS 1024
#define N_SCAN_BLOCKS ((N_NODES + SCAN_BS - 1) / SCAN_BS)   // 98

#define PDL_WAIT()    asm volatile("griddepcontrol.wait;" ::: "memory")
#define PDL_TRIGGER() asm volatile("griddepcontrol.launch_dependents;" ::: "memory")

// Static scratch (no allocation allowed). All state self-restoring per call:
// deg reset in k_scan_off; g_bpub reset by k_scatter's first 98 threads.
__device__ __half g_hX[(size_t)N_NODES * D_FEAT];
__device__ __half g_h1[(size_t)N_NODES * D_FEAT];
__device__ __half g_h2[(size_t)N_NODES * D_FEAT];
__device__ int    g_deg[N_NODES];
__device__ int    g_off[N_NODES + 1];
__device__ int    g_rank[MAX_E];
__device__ int2   g_sedge[MAX_E];
__device__ unsigned long long g_bpub[N_SCAN_BLOCKS];   // (flag=1)<<32 | blockSum

// ---- prep: fp32->fp16 convert of X + dst histogram (return value = rank) ----
__global__ void k_prep(const float* __restrict__ X, __half* __restrict__ hX,
                       const int* __restrict__ dst, int n8, int nE) {
    PDL_WAIT();
    int i = blockIdx.x * blockDim.x + threadIdx.x;
    if (i < n8) {
        const float4* x4 = reinterpret_cast<const float4*>(X);
        float4 a = x4[2 * i];
        float4 b = x4[2 * i + 1];
        __half2 h0 = __floats2half2_rn(a.x, a.y);
        __half2 h1 = __floats2half2_rn(a.z, a.w);
        __half2 h2 = __floats2half2_rn(b.x, b.y);
        __half2 h3 = __floats2half2_rn(b.z, b.w);
        uint4 r;
        r.x = *reinterpret_cast<unsigned*>(&h0);
        r.y = *reinterpret_cast<unsigned*>(&h1);
        r.z = *reinterpret_cast<unsigned*>(&h2);
        r.w = *reinterpret_cast<unsigned*>(&h3);
        reinterpret_cast<uint4*>(hX)[i] = r;
    }
    if (i < nE) g_rank[i] = atomicAdd(&g_deg[dst[i]], 1);
    PDL_TRIGGER();
}

// ---- fused scan + finalize (decoupled lookback), writes g_off; resets deg.
//      98 blocks of 1024 — all co-resident (<= 148 SMs), so spins are safe. ----
__global__ void k_scan_off(int n, int nE) {
    PDL_WAIT();
    __shared__ int warpSums[32];
    __shared__ int redbuf[32];
    __shared__ int s_base;
    int t = threadIdx.x;
    int b = blockIdx.x;
    int i = b * SCAN_BS + t;
    int lane = t & 31;
    int wid  = t >> 5;
    int v = (i < n) ? g_deg[i] : 0;

    // warp inclusive scan
    int s = v;
    #pragma unroll
    for (int d = 1; d < 32; d <<= 1) {
        int x = __shfl_up_sync(0xffffffffu, s, d);
        if (lane >= d) s += x;
    }
    if (lane == 31) warpSums[wid] = s;
    __syncthreads();

    // warp 0: scan the 32 warp sums; publish block total (flag|sum, one word)
    if (wid == 0) {
        int ws = warpSums[lane];
        int p = ws;
        #pragma unroll
        for (int d = 1; d < 32; d <<= 1) {
            int x = __shfl_up_sync(0xffffffffu, p, d);
            if (lane >= d) p += x;
        }
        warpSums[lane] = p - ws;   // exclusive base per warp
        if (lane == 31)
            g_bpub[b] = (1ull << 32) | (unsigned long long)(unsigned)p;
    }
    __syncthreads();

    // lookback: thread j (< b) spins for predecessor j's publish word
    int contrib = 0;
    if (t < b) {
        unsigned long long w;
        do {
            w = ((volatile unsigned long long*)g_bpub)[t];
            if ((w >> 32) == 0ull) __nanosleep(32);
        } while ((w >> 32) == 0ull);
        contrib = (int)(w & 0xffffffffull);
    }
    // block-reduce contrib (only threads < 98 are nonzero)
    #pragma unroll
    for (int o = 16; o; o >>= 1) contrib += __shfl_down_sync(0xffffffffu, contrib, o);
    if (lane == 0) redbuf[wid] = contrib;
    __syncthreads();
    if (t == 0) {
        int acc = 0;
        #pragma unroll
        for (int j = 0; j < 32; j++) acc += redbuf[j];
        s_base = acc;
    }
    __syncthreads();

    if (i < n) {
        g_off[i] = s_base + warpSums[wid] + (s - v);   // global exclusive prefix
        g_deg[i] = 0;                                  // self-restore
    }
    if (b == 0 && t == 0) g_off[n] = nE;
    PDL_TRIGGER();
}

// ---- scatter: pure streaming, NO atomics; also resets the publish words ----
__global__ void k_scatter(const int* __restrict__ src,
                          const int* __restrict__ dst,
                          const float* __restrict__ ew, int nE) {
    PDL_WAIT();
    int e = blockIdx.x * blockDim.x + threadIdx.x;
    if (e < N_SCAN_BLOCKS) g_bpub[e] = 0ull;   // restore lookback state
    if (e < nE) {
        int pos = g_off[dst[e]] + g_rank[e];
        g_sedge[pos] = make_int2(src[e], __float_as_int(ew[e]));
    }
    PDL_TRIGGER();
}

// ---------------- Pull SpMM (R13 form, untouched) ----------------
// One warp per dst node. Lanes 0-15 = even edges, lanes 16-31 = odd edges.
// Lane c owns features [4c,4c+4): 16 lanes x 8B = the full 128B fp16 row.

__device__ __forceinline__ float4 warp_node_reduce_h(const __half* __restrict__ Hin,
                                                     int node, int c, int half) {
    int begin = g_off[node], end = g_off[node + 1];
    float4 acc = make_float4(0.f, 0.f, 0.f, 0.f);
    for (int e = begin + half; e < end; e += 2) {
        int2  p = g_sedge[e];
        float w = __int_as_float(p.y);
        uint2 u = reinterpret_cast<const uint2*>(Hin + (size_t)p.x * D_FEAT)[c];
        float2 fa = __half22float2(*reinterpret_cast<__half2*>(&u.x));
        float2 fb = __half22float2(*reinterpret_cast<__half2*>(&u.y));
        acc.x += w * fa.x; acc.y += w * fa.y; acc.z += w * fb.x; acc.w += w * fb.y;
    }
    acc.x += __shfl_xor_sync(0xffffffff, acc.x, 16);
    acc.y += __shfl_xor_sync(0xffffffff, acc.y, 16);
    acc.z += __shfl_xor_sync(0xffffffff, acc.z, 16);
    acc.w += __shfl_xor_sync(0xffffffff, acc.w, 16);
    return acc;
}

// Intermediate layer: write fp16 only.
__global__ void k_pull_h(const __half* __restrict__ Hin,
                         __half* __restrict__ Hout) {
    PDL_WAIT();
    int gwarp = (blockIdx.x * blockDim.x + threadIdx.x) >> 5;
    if (gwarp < N_NODES) {
        int lane = threadIdx.x & 31;
        int half = lane >> 4;
        int c    = lane & 15;
        float4 acc = warp_node_reduce_h(Hin, gwarp, c, half);
        if (half == 0) {
            __half2 h0 = __floats2half2_rn(acc.x, acc.y);
            __half2 h1 = __floats2half2_rn(acc.z, acc.w);
            uint2 u;
            u.x = *reinterpret_cast<unsigned*>(&h0);
            u.y = *reinterpret_cast<unsigned*>(&h1);
            reinterpret_cast<uint2*>(Hout + (size_t)gwarp * D_FEAT)[c] = u;
        }
    }
    PDL_TRIGGER();
}

// Final layer fused with the mean: out = 0.25*(X + h1 + h2 + h3).
__global__ void k_pull_final_h(const __half* __restrict__ Hin,   // h2 (fp16)
                               const float* __restrict__ X,
                               const __half* __restrict__ H1,
                               float* __restrict__ out) {
    PDL_WAIT();
    int gwarp = (blockIdx.x * blockDim.x + threadIdx.x) >> 5;
    if (gwarp >= N_NODES) return;
    int lane = threadIdx.x & 31;
    int half = lane >> 4;
    int c    = lane & 15;
    float4 acc = warp_node_reduce_h(Hin, gwarp, c, half);   // h3 chunk
    if (half == 0) {
        size_t idx = (size_t)gwarp * D_FEAT + (c << 2);
        float4 x0 = *reinterpret_cast<const float4*>(X + idx);
        uint2 u1 = reinterpret_cast<const uint2*>(H1  + (size_t)gwarp * D_FEAT)[c];
        uint2 u2 = reinterpret_cast<const uint2*>(Hin + (size_t)gwarp * D_FEAT)[c];
        float2 a1 = __half22float2(*reinterpret_cast<__half2*>(&u1.x));
        float2 b1 = __half22float2(*reinterpret_cast<__half2*>(&u1.y));
        float2 a2 = __half22float2(*reinterpret_cast<__half2*>(&u2.x));
        float2 b2 = __half22float2(*reinterpret_cast<__half2*>(&u2.y));
        float4 o;
        o.x = 0.25f * (x0.x + a1.x + a2.x + acc.x);
        o.y = 0.25f * (x0.y + a1.y + a2.y + acc.y);
        o.z = 0.25f * (x0.z + b1.x + b2.x + acc.z);
        o.w = 0.25f * (x0.w + b1.y + b2.y + acc.w);
        *reinterpret_cast<float4*>(out + idx) = o;
    }
}

// PDL launch helper: allow this kernel to start scheduling while the
// predecessor's tail blocks drain (dependent still waits in griddepcontrol.wait).
template <typename... Args>
static void launch_pdl(void (*kern)(Args...), dim3 grid, dim3 block, Args... args) {
    cudaLaunchConfig_t cfg = {};
    cfg.gridDim = grid;
    cfg.blockDim = block;
    cfg.dynamicSmemBytes = 0;
    cfg.stream = 0;
    cudaLaunchAttribute attr[1];
    attr[0].id = cudaLaunchAttributeProgrammaticStreamSerialization;
    attr[0].val.programmaticStreamSerializationAllowed = 1;
    cfg.attrs = attr;
    cfg.numAttrs = 1;
    cudaLaunchKernelEx(&cfg, kern, args...);
}

extern "C" void kernel_launch(void* const* d_in, const int* in_sizes, int n_in,
                              void* d_out, int out_size) {
    const float* X   = (const float*)d_in[0];
    const int*   src = (const int*)  d_in[1];
    const int*   dst = (const int*)  d_in[2];
    const float* ew  = (const float*)d_in[3];
    float* out = (float*)d_out;
    const int nE = in_sizes[1];

    __half* hX = nullptr;
    __half* h1 = nullptr;
    __half* h2 = nullptr;
    cudaGetSymbolAddress((void**)&hX, g_hX);
    cudaGetSymbolAddress((void**)&h1, g_h1);
    cudaGetSymbolAddress((void**)&h2, g_h2);

    const int TB = 256;
    const int n8       = N_NODES * D_FEAT / 8;
    const int prepN    = (nE > n8) ? nE : n8;
    const int gridPrep = (prepN + TB - 1) / TB;
    const int gridE    = (nE + TB - 1) / TB;
    const int gridPull = (N_NODES * 32 + TB - 1) / TB;   // warp per node

    // --- build dst-sorted CSR (PDL-chained) ---
    launch_pdl(k_prep, dim3(gridPrep), dim3(TB),
               (const float*)X, (__half*)hX, (const int*)dst, (int)n8, (int)nE);
    launch_pdl(k_scan_off, dim3(N_SCAN_BLOCKS), dim3(SCAN_BS),
               (int)N_NODES, (int)nE);
    launch_pdl(k_scatter, dim3(gridE), dim3(TB),
               (const int*)src, (const int*)dst, (const float*)ew, (int)nE);

    // --- 3 pull layers (PDL-chained; fp16 gathers, fp32 accum + mean) ---
    launch_pdl(k_pull_h, dim3(gridPull), dim3(TB),
               (const __half*)hX, (__half*)h1);
    launch_pdl(k_pull_h, dim3(gridPull), dim3(TB),
               (const __half*)h1, (__half*)h2);
    launch_pdl(k_pull_final_h, dim3(gridPull), dim3(TB),
               (const __half*)h2, (const float*)X, (const __half*)h1, (float*)out);
}

// round 16
// speedup vs baseline: 1.0807x; 1.0807x over previous
#include <cuda_runtime.h>
#include <cuda_fp16.h>
#include <cstdint>

// LightGCN: out = 0.25*(X + h1 + h2 + h3), h_{k+1} = A h_k  (FINAL = R13, best measured 135.3us)
// Pull-based dst-sorted CSR built per launch (atomic-free feature path),
// fp16 gather operands/intermediates, fp32 accumulation + exact fp32 X in mean.
//
// Falsified alternatives (kept for the record):
//  - scatter-atomic SpMM (R1: 311us), manual ILP in pull loop (R3/R12: regress),
//  - monolithic persistent kernel (R9: occ-starved pulls), build-only coop
//    kernel (R10), 8-lane uint4 pull (R11), PDL chaining (R15: occ-stealing).

#define N_NODES 100000
#define D_FEAT  64
#define MAX_E   1600000
#define SCAN_BS 1024
#define N_SCAN_BLOCKS ((N_NODES + SCAN_BS - 1) / SCAN_BS)   // 98

// Static scratch (no allocation allowed). deg self-restores each call.
__device__ __half g_hX[(size_t)N_NODES * D_FEAT];
__device__ __half g_h1[(size_t)N_NODES * D_FEAT];
__device__ __half g_h2[(size_t)N_NODES * D_FEAT];
__device__ int    g_deg[N_NODES];
__device__ int    g_exloc[N_NODES];
__device__ int    g_blockSums[N_SCAN_BLOCKS];
__device__ int    g_off[N_NODES + 1];
__device__ int    g_rank[MAX_E];
__device__ int2   g_sedge[MAX_E];

// ---- prep: fp32->fp16 convert of X + dst histogram (return value = rank) ----
__global__ void k_prep(const float* __restrict__ X, __half* __restrict__ hX,
                       const int* __restrict__ dst, int n8, int nE) {
    int i = blockIdx.x * blockDim.x + threadIdx.x;
    if (i < n8) {
        const float4* x4 = reinterpret_cast<const float4*>(X);
        float4 a = x4[2 * i];
        float4 b = x4[2 * i + 1];
        __half2 h0 = __floats2half2_rn(a.x, a.y);
        __half2 h1 = __floats2half2_rn(a.z, a.w);
        __half2 h2 = __floats2half2_rn(b.x, b.y);
        __half2 h3 = __floats2half2_rn(b.z, b.w);
        uint4 r;
        r.x = *reinterpret_cast<unsigned*>(&h0);
        r.y = *reinterpret_cast<unsigned*>(&h1);
        r.z = *reinterpret_cast<unsigned*>(&h2);
        r.w = *reinterpret_cast<unsigned*>(&h3);
        reinterpret_cast<uint4*>(hX)[i] = r;
    }
    if (i < nE) g_rank[i] = atomicAdd(&g_deg[dst[i]], 1);
}

// ---- per-block scan via warp shuffles: block-local EXCLUSIVE prefix +
//      block sums; resets deg. 2 __syncthreads total. ----
__global__ void k_scan_block(int n) {
    __shared__ int warpSums[32];
    int t = threadIdx.x;
    int i = blockIdx.x * SCAN_BS + t;
    int lane = t & 31;
    int wid  = t >> 5;
    int v = (i < n) ? g_deg[i] : 0;

    // warp inclusive scan
    int s = v;
    #pragma unroll
    for (int d = 1; d < 32; d <<= 1) {
        int x = __shfl_up_sync(0xffffffffu, s, d);
        if (lane >= d) s += x;
    }
    if (lane == 31) warpSums[wid] = s;
    __syncthreads();

    // warp 0 scans the 32 warp sums (exclusive)
    if (wid == 0) {
        int ws = warpSums[lane];
        int p = ws;
        #pragma unroll
        for (int d = 1; d < 32; d <<= 1) {
            int x = __shfl_up_sync(0xffffffffu, p, d);
            if (lane >= d) p += x;
        }
        warpSums[lane] = p - ws;   // exclusive base per warp
        if (lane == 31) g_blockSums[blockIdx.x] = p;   // block total
    }
    __syncthreads();

    if (i < n) {
        g_exloc[i] = warpSums[wid] + s - v;   // block-local exclusive
        g_deg[i] = 0;                         // self-restore for next replay
    }
}

// ---- finalize: recompute chunk base from the 98 block sums; write off ----
__global__ void k_finalize(int n, int nE) {
    __shared__ int s_base;
    int chunk = blockIdx.x >> 2;
    if (threadIdx.x < 32) {
        int acc = 0;
        for (int j = (int)threadIdx.x; j < chunk; j += 32) acc += g_blockSums[j];
        #pragma unroll
        for (int o = 16; o; o >>= 1) acc += __shfl_down_sync(0xffffffffu, acc, o);
        if (threadIdx.x == 0) s_base = acc;
    }
    __syncthreads();
    int i = blockIdx.x * 256 + threadIdx.x;
    if (i >= n) return;
    g_off[i] = g_exloc[i] + s_base;
    if (i == n - 1) g_off[n] = nE;
}

// ---- scatter: pure streaming, NO atomics ----
__global__ void k_scatter(const int* __restrict__ src,
                          const int* __restrict__ dst,
                          const float* __restrict__ ew, int nE) {
    int e = blockIdx.x * blockDim.x + threadIdx.x;
    if (e >= nE) return;
    int pos = g_off[dst[e]] + g_rank[e];
    g_sedge[pos] = make_int2(src[e], __float_as_int(ew[e]));
}

// ---------------- Pull SpMM (fp16 gathers, fp32 accumulate) ----------------
// One warp per dst node. Lanes 0-15 = even edges, lanes 16-31 = odd edges.
// Lane c owns features [4c,4c+4): 16 lanes x 8B = the full 128B fp16 row.

__device__ __forceinline__ float4 warp_node_reduce_h(const __half* __restrict__ Hin,
                                                     int node, int c, int half) {
    int begin = g_off[node], end = g_off[node + 1];
    float4 acc = make_float4(0.f, 0.f, 0.f, 0.f);
    for (int e = begin + half; e < end; e += 2) {
        int2  p = g_sedge[e];
        float w = __int_as_float(p.y);
        uint2 u = reinterpret_cast<const uint2*>(Hin + (size_t)p.x * D_FEAT)[c];
        float2 fa = __half22float2(*reinterpret_cast<__half2*>(&u.x));
        float2 fb = __half22float2(*reinterpret_cast<__half2*>(&u.y));
        acc.x += w * fa.x; acc.y += w * fa.y; acc.z += w * fb.x; acc.w += w * fb.y;
    }
    acc.x += __shfl_xor_sync(0xffffffff, acc.x, 16);
    acc.y += __shfl_xor_sync(0xffffffff, acc.y, 16);
    acc.z += __shfl_xor_sync(0xffffffff, acc.z, 16);
    acc.w += __shfl_xor_sync(0xffffffff, acc.w, 16);
    return acc;
}

// Intermediate layer: write fp16 only.
__global__ void k_pull_h(const __half* __restrict__ Hin,
                         __half* __restrict__ Hout) {
    int gwarp = (blockIdx.x * blockDim.x + threadIdx.x) >> 5;
    if (gwarp >= N_NODES) return;
    int lane = threadIdx.x & 31;
    int half = lane >> 4;
    int c    = lane & 15;
    float4 acc = warp_node_reduce_h(Hin, gwarp, c, half);
    if (half == 0) {
        __half2 h0 = __floats2half2_rn(acc.x, acc.y);
        __half2 h1 = __floats2half2_rn(acc.z, acc.w);
        uint2 u;
        u.x = *reinterpret_cast<unsigned*>(&h0);
        u.y = *reinterpret_cast<unsigned*>(&h1);
        reinterpret_cast<uint2*>(Hout + (size_t)gwarp * D_FEAT)[c] = u;
    }
}

// Final layer fused with the mean: out = 0.25*(X + h1 + h2 + h3).
__global__ void k_pull_final_h(const __half* __restrict__ Hin,   // h2 (fp16)
                               const float* __restrict__ X,
                               const __half* __restrict__ H1,
                               float* __restrict__ out) {
    int gwarp = (blockIdx.x * blockDim.x + threadIdx.x) >> 5;
    if (gwarp >= N_NODES) return;
    int lane = threadIdx.x & 31;
    int half = lane >> 4;
    int c    = lane & 15;
    float4 acc = warp_node_reduce_h(Hin, gwarp, c, half);   // h3 chunk
    if (half == 0) {
        size_t idx = (size_t)gwarp * D_FEAT + (c << 2);
        float4 x0 = *reinterpret_cast<const float4*>(X + idx);
        uint2 u1 = reinterpret_cast<const uint2*>(H1  + (size_t)gwarp * D_FEAT)[c];
        uint2 u2 = reinterpret_cast<const uint2*>(Hin + (size_t)gwarp * D_FEAT)[c];
        float2 a1 = __half22float2(*reinterpret_cast<__half2*>(&u1.x));
        float2 b1 = __half22float2(*reinterpret_cast<__half2*>(&u1.y));
        float2 a2 = __half22float2(*reinterpret_cast<__half2*>(&u2.x));
        float2 b2 = __half22float2(*reinterpret_cast<__half2*>(&u2.y));
        float4 o;
        o.x = 0.25f * (x0.x + a1.x + a2.x + acc.x);
        o.y = 0.25f * (x0.y + a1.y + a2.y + acc.y);
        o.z = 0.25f * (x0.z + b1.x + b2.x + acc.z);
        o.w = 0.25f * (x0.w + b1.y + b2.y + acc.w);
        *reinterpret_cast<float4*>(out + idx) = o;
    }
}

extern "C" void kernel_launch(void* const* d_in, const int* in_sizes, int n_in,
                              void* d_out, int out_size) {
    const float* X   = (const float*)d_in[0];
    const int*   src = (const int*)  d_in[1];
    const int*   dst = (const int*)  d_in[2];
    const float* ew  = (const float*)d_in[3];
    float* out = (float*)d_out;
    const int nE = in_sizes[1];

    __half* hX = nullptr;
    __half* h1 = nullptr;
    __half* h2 = nullptr;
    cudaGetSymbolAddress((void**)&hX, g_hX);
    cudaGetSymbolAddress((void**)&h1, g_h1);
    cudaGetSymbolAddress((void**)&h2, g_h2);

    const int TB = 256;
    const int n8       = N_NODES * D_FEAT / 8;
    const int prepN    = (nE > n8) ? nE : n8;
    const int gridPrep = (prepN + TB - 1) / TB;
    const int gridFin  = (N_NODES + 255) / 256;
    const int gridE    = (nE + TB - 1) / TB;
    const int gridPull = (N_NODES * 32 + TB - 1) / TB;   // warp per node

    // --- build dst-sorted CSR ---
    k_prep<<<gridPrep, TB>>>(X, hX, dst, n8, nE);
    k_scan_block<<<N_SCAN_BLOCKS, SCAN_BS>>>(N_NODES);
    k_finalize<<<gridFin, 256>>>(N_NODES, nE);
    k_scatter<<<gridE, TB>>>(src, dst, ew, nE);

    // --- 3 pull layers (fp16 gathers, fp32 accumulation + mean) ---
    k_pull_h<<<gridPull, TB>>>(hX, h1);
    k_pull_h<<<gridPull, TB>>>(h1, h2);
    k_pull_final_h<<<gridPull, TB>>>(h2, X, h1, out);
}

// round 17
// speedup vs baseline: 1.1180x; 1.0345x over previous
#include <cuda_runtime.h>
#include <cuda_fp16.h>
#include <cstdint>

// LightGCN: out = 0.25*(X + h1 + h2 + h3), h_{k+1} = A h_k
// R17 = R13/R16 (twice-measured 135.26us) with ONE change: pull kernels launch
// with 128-thread blocks (4 node-warps) instead of 256 (8) to reduce
// degree-imbalance straggling at block-retirement granularity.

#define N_NODES 100000
#define D_FEAT  64
#define MAX_E   1600000
#define SCAN_BS 1024
#define N_SCAN_BLOCKS ((N_NODES + SCAN_BS - 1) / SCAN_BS)   // 98

// Static scratch (no allocation allowed). deg self-restores each call.
__device__ __half g_hX[(size_t)N_NODES * D_FEAT];
__device__ __half g_h1[(size_t)N_NODES * D_FEAT];
__device__ __half g_h2[(size_t)N_NODES * D_FEAT];
__device__ int    g_deg[N_NODES];
__device__ int    g_exloc[N_NODES];
__device__ int    g_blockSums[N_SCAN_BLOCKS];
__device__ int    g_off[N_NODES + 1];
__device__ int    g_rank[MAX_E];
__device__ int2   g_sedge[MAX_E];

// ---- prep: fp32->fp16 convert of X + dst histogram (return value = rank) ----
__global__ void k_prep(const float* __restrict__ X, __half* __restrict__ hX,
                       const int* __restrict__ dst, int n8, int nE) {
    int i = blockIdx.x * blockDim.x + threadIdx.x;
    if (i < n8) {
        const float4* x4 = reinterpret_cast<const float4*>(X);
        float4 a = x4[2 * i];
        float4 b = x4[2 * i + 1];
        __half2 h0 = __floats2half2_rn(a.x, a.y);
        __half2 h1 = __floats2half2_rn(a.z, a.w);
        __half2 h2 = __floats2half2_rn(b.x, b.y);
        __half2 h3 = __floats2half2_rn(b.z, b.w);
        uint4 r;
        r.x = *reinterpret_cast<unsigned*>(&h0);
        r.y = *reinterpret_cast<unsigned*>(&h1);
        r.z = *reinterpret_cast<unsigned*>(&h2);
        r.w = *reinterpret_cast<unsigned*>(&h3);
        reinterpret_cast<uint4*>(hX)[i] = r;
    }
    if (i < nE) g_rank[i] = atomicAdd(&g_deg[dst[i]], 1);
}

// ---- per-block scan via warp shuffles: block-local EXCLUSIVE prefix +
//      block sums; resets deg. 2 __syncthreads total. ----
__global__ void k_scan_block(int n) {
    __shared__ int warpSums[32];
    int t = threadIdx.x;
    int i = blockIdx.x * SCAN_BS + t;
    int lane = t & 31;
    int wid  = t >> 5;
    int v = (i < n) ? g_deg[i] : 0;

    // warp inclusive scan
    int s = v;
    #pragma unroll
    for (int d = 1; d < 32; d <<= 1) {
        int x = __shfl_up_sync(0xffffffffu, s, d);
        if (lane >= d) s += x;
    }
    if (lane == 31) warpSums[wid] = s;
    __syncthreads();

    // warp 0 scans the 32 warp sums (exclusive)
    if (wid == 0) {
        int ws = warpSums[lane];
        int p = ws;
        #pragma unroll
        for (int d = 1; d < 32; d <<= 1) {
            int x = __shfl_up_sync(0xffffffffu, p, d);
            if (lane >= d) p += x;
        }
        warpSums[lane] = p - ws;   // exclusive base per warp
        if (lane == 31) g_blockSums[blockIdx.x] = p;   // block total
    }
    __syncthreads();

    if (i < n) {
        g_exloc[i] = warpSums[wid] + s - v;   // block-local exclusive
        g_deg[i] = 0;                         // self-restore for next replay
    }
}

// ---- finalize: recompute chunk base from the 98 block sums; write off ----
__global__ void k_finalize(int n, int nE) {
    __shared__ int s_base;
    int chunk = blockIdx.x >> 2;
    if (threadIdx.x < 32) {
        int acc = 0;
        for (int j = (int)threadIdx.x; j < chunk; j += 32) acc += g_blockSums[j];
        #pragma unroll
        for (int o = 16; o; o >>= 1) acc += __shfl_down_sync(0xffffffffu, acc, o);
        if (threadIdx.x == 0) s_base = acc;
    }
    __syncthreads();
    int i = blockIdx.x * 256 + threadIdx.x;
    if (i >= n) return;
    g_off[i] = g_exloc[i] + s_base;
    if (i == n - 1) g_off[n] = nE;
}

// ---- scatter: pure streaming, NO atomics ----
__global__ void k_scatter(const int* __restrict__ src,
                          const int* __restrict__ dst,
                          const float* __restrict__ ew, int nE) {
    int e = blockIdx.x * blockDim.x + threadIdx.x;
    if (e >= nE) return;
    int pos = g_off[dst[e]] + g_rank[e];
    g_sedge[pos] = make_int2(src[e], __float_as_int(ew[e]));
}

// ---------------- Pull SpMM (fp16 gathers, fp32 accumulate) ----------------
// One warp per dst node. Lanes 0-15 = even edges, lanes 16-31 = odd edges.
// Lane c owns features [4c,4c+4): 16 lanes x 8B = the full 128B fp16 row.

__device__ __forceinline__ float4 warp_node_reduce_h(const __half* __restrict__ Hin,
                                                     int node, int c, int half) {
    int begin = g_off[node], end = g_off[node + 1];
    float4 acc = make_float4(0.f, 0.f, 0.f, 0.f);
    for (int e = begin + half; e < end; e += 2) {
        int2  p = g_sedge[e];
        float w = __int_as_float(p.y);
        uint2 u = reinterpret_cast<const uint2*>(Hin + (size_t)p.x * D_FEAT)[c];
        float2 fa = __half22float2(*reinterpret_cast<__half2*>(&u.x));
        float2 fb = __half22float2(*reinterpret_cast<__half2*>(&u.y));
        acc.x += w * fa.x; acc.y += w * fa.y; acc.z += w * fb.x; acc.w += w * fb.y;
    }
    acc.x += __shfl_xor_sync(0xffffffff, acc.x, 16);
    acc.y += __shfl_xor_sync(0xffffffff, acc.y, 16);
    acc.z += __shfl_xor_sync(0xffffffff, acc.z, 16);
    acc.w += __shfl_xor_sync(0xffffffff, acc.w, 16);
    return acc;
}

// Intermediate layer: write fp16 only.
__global__ void k_pull_h(const __half* __restrict__ Hin,
                         __half* __restrict__ Hout) {
    int gwarp = (blockIdx.x * blockDim.x + threadIdx.x) >> 5;
    if (gwarp >= N_NODES) return;
    int lane = threadIdx.x & 31;
    int half = lane >> 4;
    int c    = lane & 15;
    float4 acc = warp_node_reduce_h(Hin, gwarp, c, half);
    if (half == 0) {
        __half2 h0 = __floats2half2_rn(acc.x, acc.y);
        __half2 h1 = __floats2half2_rn(acc.z, acc.w);
        uint2 u;
        u.x = *reinterpret_cast<unsigned*>(&h0);
        u.y = *reinterpret_cast<unsigned*>(&h1);
        reinterpret_cast<uint2*>(Hout + (size_t)gwarp * D_FEAT)[c] = u;
    }
}

// Final layer fused with the mean: out = 0.25*(X + h1 + h2 + h3).
__global__ void k_pull_final_h(const __half* __restrict__ Hin,   // h2 (fp16)
                               const float* __restrict__ X,
                               const __half* __restrict__ H1,
                               float* __restrict__ out) {
    int gwarp = (blockIdx.x * blockDim.x + threadIdx.x) >> 5;
    if (gwarp >= N_NODES) return;
    int lane = threadIdx.x & 31;
    int half = lane >> 4;
    int c    = lane & 15;
    float4 acc = warp_node_reduce_h(Hin, gwarp, c, half);   // h3 chunk
    if (half == 0) {
        size_t idx = (size_t)gwarp * D_FEAT + (c << 2);
        float4 x0 = *reinterpret_cast<const float4*>(X + idx);
        uint2 u1 = reinterpret_cast<const uint2*>(H1  + (size_t)gwarp * D_FEAT)[c];
        uint2 u2 = reinterpret_cast<const uint2*>(Hin + (size_t)gwarp * D_FEAT)[c];
        float2 a1 = __half22float2(*reinterpret_cast<__half2*>(&u1.x));
        float2 b1 = __half22float2(*reinterpret_cast<__half2*>(&u1.y));
        float2 a2 = __half22float2(*reinterpret_cast<__half2*>(&u2.x));
        float2 b2 = __half22float2(*reinterpret_cast<__half2*>(&u2.y));
        float4 o;
        o.x = 0.25f * (x0.x + a1.x + a2.x + acc.x);
        o.y = 0.25f * (x0.y + a1.y + a2.y + acc.y);
        o.z = 0.25f * (x0.z + b1.x + b2.x + acc.z);
        o.w = 0.25f * (x0.w + b1.y + b2.y + acc.w);
        *reinterpret_cast<float4*>(out + idx) = o;
    }
}

extern "C" void kernel_launch(void* const* d_in, const int* in_sizes, int n_in,
                              void* d_out, int out_size) {
    const float* X   = (const float*)d_in[0];
    const int*   src = (const int*)  d_in[1];
    const int*   dst = (const int*)  d_in[2];
    const float* ew  = (const float*)d_in[3];
    float* out = (float*)d_out;
    const int nE = in_sizes[1];

    __half* hX = nullptr;
    __half* h1 = nullptr;
    __half* h2 = nullptr;
    cudaGetSymbolAddress((void**)&hX, g_hX);
    cudaGetSymbolAddress((void**)&h1, g_h1);
    cudaGetSymbolAddress((void**)&h2, g_h2);

    const int TB  = 256;
    const int TBP = 128;                                   // pull blocks: 4 warps
    const int n8       = N_NODES * D_FEAT / 8;
    const int prepN    = (nE > n8) ? nE : n8;
    const int gridPrep = (prepN + TB - 1) / TB;
    const int gridFin  = (N_NODES + 255) / 256;
    const int gridE    = (nE + TB - 1) / TB;
    const int gridPull = (N_NODES * 32 + TBP - 1) / TBP;   // warp per node

    // --- build dst-sorted CSR ---
    k_prep<<<gridPrep, TB>>>(X, hX, dst, n8, nE);
    k_scan_block<<<N_SCAN_BLOCKS, SCAN_BS>>>(N_NODES);
    k_finalize<<<gridFin, 256>>>(N_NODES, nE);
    k_scatter<<<gridE, TB>>>(src, dst, ew, nE);

    // --- 3 pull layers (fp16 gathers, fp32 accumulation + mean) ---
    k_pull_h<<<gridPull, TBP>>>(hX, h1);
    k_pull_h<<<gridPull, TBP>>>(h1, h2);
    k_pull_final_h<<<gridPull, TBP>>>(h2, X, h1, out);
}